// round 3
// baseline (speedup 1.0000x reference)
#include <cuda_runtime.h>
#include <math.h>

// YOLOv1 loss — streaming decomposition.
//
// Separable parts (cls over ch10-29, noobj over ch4/9) are computed by a
// barrier-free warp-per-cell streaming kernel (A). Obj cells (~20%) spill
// their 20 box floats (pred ch0-9, target ch0-9) to a compacted per-sample
// scratch buffer. Kernel B does the IoU-existence pairing on the compacted
// boxes only. Kernel C reduces and restores scratch state for graph replay.
//
// Exactness: max_iou is only compared against 0 and union>0 always (w,h>=0.05),
// so cmask == "exists masked pred box with intersection>0". The intersection
// arithmetic (cx - 0.5f*w etc., min/max/sub, >0) is bit-identical to the
// reference's decision. Box values pass through the scratch buffer unmodified.

#define CELLS 49
#define CH 30
#define FPS (CELLS * CH)      // 1470
#define MAXB 8192
#define NSLOT 128

__device__ float  g_boxes[MAXB * CELLS * 20];   // 32 MB scratch, compacted records
__device__ int    g_boxcnt[MAXB];               // zero-initialized; B resets after use
__device__ double g_acc[4 * NSLOT];             // [0]=noobj [1]=cls [2]=coord [3]=objconf

// ---------------------------------------------------------------------------
// Kernel A: warp-per-cell streaming. lane = channel (lanes 30,31 idle on load).
// ---------------------------------------------------------------------------
__global__ __launch_bounds__(256) void yolo_stream_kernel(
    const float* __restrict__ pred, const float* __restrict__ target,
    int ncells, int nwarps)
{
    const int lane = threadIdx.x & 31;
    const int wid  = threadIdx.x >> 5;
    int cell = ((blockIdx.x * 256 + threadIdx.x) >> 5);

    float accN = 0.f, accC = 0.f;

    // software-pipelined 1-ahead
    float p = 0.f, t = 0.f, t4 = 0.f;
    if (cell < ncells) {
        const int base = cell * CH;
        if (lane < CH) { p = pred[base + lane]; t = target[base + lane]; }
        t4 = target[base + 4];
    }

    while (cell < ncells) {
        const int nxt = cell + nwarps;
        float np = 0.f, nt = 0.f, nt4 = 0.f;
        if (nxt < ncells) {
            const int nb = nxt * CH;
            if (lane < CH) { np = pred[nb + lane]; nt = target[nb + nb - nb + lane]; }
            nt4 = target[nb + 4];
        }

        // ---- process current cell ----
        const float d  = p - t;
        const float dd = d * d;
        if (t4 > 0.f) {
            if (lane >= 10 && lane < CH) accC += dd;
            // spill compacted box record (warp-uniform branch: t4 uniform)
            const int b = cell / CELLS;
            int slot = 0;
            if (lane == 0) slot = atomicAdd(&g_boxcnt[b], 1);
            slot = __shfl_sync(0xffffffffu, slot, 0);
            if (lane < 10 && b < MAXB) {
                float* rec = g_boxes + (size_t)b * (CELLS * 20) + slot * 20;
                rec[lane]      = p;   // pred ch0-9
                rec[10 + lane] = t;   // target ch0-9
            }
        } else {
            if (lane == 4 || lane == 9) accN += dd;
        }

        p = np; t = nt; t4 = nt4;
        cell = nxt;
    }

    // warp reduce 2 scalars
    #pragma unroll
    for (int o = 16; o > 0; o >>= 1) {
        accN += __shfl_down_sync(0xffffffffu, accN, o);
        accC += __shfl_down_sync(0xffffffffu, accC, o);
    }
    __shared__ float sN[8], sC[8];
    if (lane == 0) { sN[wid] = accN; sC[wid] = accC; }
    __syncthreads();
    if (threadIdx.x == 0) {
        float n = 0.f, c = 0.f;
        #pragma unroll
        for (int w = 0; w < 8; w++) { n += sN[w]; c += sC[w]; }
        const int slot = blockIdx.x & (NSLOT - 1);
        atomicAdd(&g_acc[0 * NSLOT + slot], (double)n);
        atomicAdd(&g_acc[1 * NSLOT + slot], (double)c);
    }
}

// ---------------------------------------------------------------------------
// Kernel B: warp-per-sample pairing on compacted boxes.
// ---------------------------------------------------------------------------
__global__ __launch_bounds__(256) void yolo_pair_kernel(int B)
{
    const int lane = threadIdx.x & 31;
    const int b = blockIdx.x * 8 + (threadIdx.x >> 5);
    if (b >= B) return;

    const int   cnt  = g_boxcnt[b];
    const int   nbox = 2 * cnt;
    const float* base = g_boxes + (size_t)b * (CELLS * 20);

    float coord = 0.f, objc = 0.f;

    for (int i = lane; i < nbox; i += 32) {
        const int roff = (i >> 1) * 20 + 5 * (i & 1);
        // target box i (xyxy, reference-exact ops)
        const float tcx = base[roff + 10], tcy = base[roff + 11];
        const float tw  = base[roff + 12], th  = base[roff + 13];
        const float tx0 = tcx - 0.5f * tw, ty0 = tcy - 0.5f * th;
        const float tx1 = tcx + 0.5f * tw, ty1 = tcy + 0.5f * th;

        bool found = false;
        for (int j = 0; j < nbox; j++) {
            const int po = (j >> 1) * 20 + 5 * (j & 1);
            const float pcx = base[po],     pcy = base[po + 1];
            const float pw  = base[po + 2], ph  = base[po + 3];
            const float ix = fminf(pcx + 0.5f * pw, tx1) - fmaxf(pcx - 0.5f * pw, tx0);
            const float iy = fminf(pcy + 0.5f * ph, ty1) - fmaxf(pcy - 0.5f * ph, ty0);
            found = found || (ix > 0.f && iy > 0.f && ix * iy > 0.f);
        }

        if (found) {
            const float dx = base[roff + 0] - tcx;
            const float dy = base[roff + 1] - tcy;
            const float dw = sqrtf(base[roff + 2]) - sqrtf(tw);
            const float dh = sqrtf(base[roff + 3]) - sqrtf(th);
            coord += dx * dx + dy * dy + dw * dw + dh * dh;
            const float dc = base[roff + 4] - base[roff + 14];
            objc += dc * dc;
        }
    }

    #pragma unroll
    for (int o = 16; o > 0; o >>= 1) {
        coord += __shfl_down_sync(0xffffffffu, coord, o);
        objc  += __shfl_down_sync(0xffffffffu, objc, o);
    }
    if (lane == 0) {
        const int slot = b & (NSLOT - 1);
        atomicAdd(&g_acc[2 * NSLOT + slot], (double)coord);
        atomicAdd(&g_acc[3 * NSLOT + slot], (double)objc);
        g_boxcnt[b] = 0;   // restore invariant for next graph replay
    }
}

// ---------------------------------------------------------------------------
// Kernel C: final reduction + output + re-zero accumulators.
// ---------------------------------------------------------------------------
__global__ void yolo_final_kernel(float* __restrict__ out, int B)
{
    const int t = threadIdx.x;            // blockDim = 128
    const int lane = t & 31, warp = t >> 5;
    double v0 = g_acc[0 * NSLOT + t];
    double v1 = g_acc[1 * NSLOT + t];
    double v2 = g_acc[2 * NSLOT + t];
    double v3 = g_acc[3 * NSLOT + t];
    // each thread read its own slots; zero them now (no races)
    g_acc[0 * NSLOT + t] = 0.0;
    g_acc[1 * NSLOT + t] = 0.0;
    g_acc[2 * NSLOT + t] = 0.0;
    g_acc[3 * NSLOT + t] = 0.0;

    #pragma unroll
    for (int o = 16; o > 0; o >>= 1) {
        v0 += __shfl_down_sync(0xffffffffu, v0, o);
        v1 += __shfl_down_sync(0xffffffffu, v1, o);
        v2 += __shfl_down_sync(0xffffffffu, v2, o);
        v3 += __shfl_down_sync(0xffffffffu, v3, o);
    }
    __shared__ double sm[4][4];
    if (lane == 0) { sm[0][warp] = v0; sm[1][warp] = v1; sm[2][warp] = v2; sm[3][warp] = v3; }
    __syncthreads();
    if (t == 0) {
        double r0 = 0, r1 = 0, r2 = 0, r3 = 0;
        #pragma unroll
        for (int w = 0; w < 4; w++) {
            r0 += sm[0][w]; r1 += sm[1][w]; r2 += sm[2][w]; r3 += sm[3][w];
        }
        const double inv = 1.0 / (double)B;
        const double cls_l = r1 * inv;
        const double obj_l = (r3 + 0.5 * r0) * inv;
        const double crd_l = r2 * 5.0 * inv;
        out[0] = (float)(cls_l + obj_l + crd_l);
        out[1] = (float)cls_l;
        out[2] = (float)obj_l;
        out[3] = (float)crd_l;
    }
}

extern "C" void kernel_launch(void* const* d_in, const int* in_sizes, int n_in,
                              void* d_out, int out_size)
{
    const float* pred = (const float*)d_in[0];
    const float* target = (const float*)d_in[1];
    const int B = in_sizes[0] / FPS;
    const int ncells = B * CELLS;

    const int nctaA = 592;                    // 4 CTAs/SM x 148 SMs
    const int nwarps = nctaA * 8;
    yolo_stream_kernel<<<nctaA, 256>>>(pred, target, ncells, nwarps);
    yolo_pair_kernel<<<(B + 7) / 8, 256>>>(B);
    yolo_final_kernel<<<1, 128>>>((float*)d_out, B);
}

// round 4
// speedup vs baseline: 1.4506x; 1.4506x over previous
#include <cuda_runtime.h>
#include <math.h>

// YOLOv1 loss — 64-cell-chunk staging kernel (A) + pairing/final kernel (B).
//
// Exactness note: max_iou is only ever compared against 0, and union>0 always
// (w,h >= 0.05), so cmask == "exists masked pred box with intersection > 0".
// The intersection arithmetic (cx - 0.5f*w, min/max/sub, >0 test) matches the
// reference ops exactly, so the decision is bit-identical. Box floats pass
// through the scratch buffer unmodified.
//
// Graph-replay invariants: g_acc / g_boxcnt / g_count are zero at the start of
// every launch; kernel B's last CTA restores all of them after use.

#define CELLS 49
#define CH 30
#define FPS (CELLS * CH)        // 1470 floats per sample
#define CHUNK 64                // cells per CTA in kernel A
#define CHUNK_F (CHUNK * CH)    // 1920 floats
#define MAXB 8192
#define NSLOT 128
#define NCTA_B_MAX ((MAXB + 7) / 8)

__device__ float  g_boxes[MAXB * CELLS * 20];       // compacted obj-box records
__device__ int    g_boxcnt[MAXB];                   // boxes per sample (zeroed by B)
__device__ double g_acc[2 * NSLOT];                 // [0]=noobj [1]=cls (zeroed by B)
__device__ float  g_partB[NCTA_B_MAX * 2];          // per-CTA coord/objc partials
__device__ unsigned int g_count = 0;

// ---------------------------------------------------------------------------
// Kernel A: one CTA per 64-cell chunk. float4 staging -> per-cell compute.
// ---------------------------------------------------------------------------
__global__ __launch_bounds__(256) void yolo_chunk_kernel(
    const float* __restrict__ pred, const float* __restrict__ target,
    int ncells, int total_floats)
{
    __shared__ float sp[CHUNK_F];
    __shared__ float st[CHUNK_F];
    __shared__ float sN[8], sC[8];

    const int tid  = threadIdx.x;
    const int c0   = blockIdx.x * CHUNK;              // first cell of this chunk
    const int f0   = c0 * CH;                         // first float (div by 4? no — 64*30=1920 div 4, and chunk idx * 1920 div 4: yes)
    const int flen = min(CHUNK_F, total_floats - f0); // floats in this chunk

    // ---- stage both tensors, float4 (chunk start is 16B aligned) ----
    {
        const int nv4 = flen >> 2;                    // full float4s
        const float4* gp4 = (const float4*)(pred + f0);
        const float4* gt4 = (const float4*)(target + f0);
        float4* sp4 = (float4*)sp;
        float4* st4 = (float4*)st;
        #pragma unroll 2
        for (int i = tid; i < nv4; i += 256) {
            sp4[i] = gp4[i];
            st4[i] = gt4[i];
        }
        for (int i = (nv4 << 2) + tid; i < flen; i += 256) {  // scalar tail (last chunk only)
            sp[i] = pred[f0 + i];
            st[i] = target[f0 + i];
        }
    }
    __syncthreads();

    // ---- per-cell compute: threads 0..63 each own one cell ----
    float accN = 0.f, accC = 0.f;
    if (tid < CHUNK && c0 + tid < ncells) {
        const int cell = c0 + tid;
        const float* pc = sp + tid * CH;
        const float* tc = st + tid * CH;
        if (tc[4] == 0.f) {                           // conf channel is exactly 0/1
            const float d4 = pc[4] - tc[4];
            const float d9 = pc[9] - tc[9];
            accN = d4 * d4 + d9 * d9;
        } else {
            float s = 0.f;
            #pragma unroll
            for (int k = 10; k < CH; k++) {
                const float d = pc[k] - tc[k];
                s += d * d;
            }
            accC = s;
            // spill compacted box record for the pairing kernel
            const int b = cell / CELLS;
            const int slot = atomicAdd(&g_boxcnt[b], 1);
            float* rec = g_boxes + (size_t)b * (CELLS * 20) + slot * 20;
            #pragma unroll
            for (int k = 0; k < 10; k++) {
                rec[k]      = pc[k];
                rec[10 + k] = tc[k];
            }
        }
    }

    // ---- block reduce 2 scalars ----
    #pragma unroll
    for (int o = 16; o > 0; o >>= 1) {
        accN += __shfl_down_sync(0xffffffffu, accN, o);
        accC += __shfl_down_sync(0xffffffffu, accC, o);
    }
    const int lane = tid & 31, warp = tid >> 5;
    if (lane == 0) { sN[warp] = accN; sC[warp] = accC; }
    __syncthreads();
    if (tid == 0) {
        float n = 0.f, c = 0.f;
        #pragma unroll
        for (int w = 0; w < 8; w++) { n += sN[w]; c += sC[w]; }
        const int slot = blockIdx.x & (NSLOT - 1);
        atomicAdd(&g_acc[0 * NSLOT + slot], (double)n);
        atomicAdd(&g_acc[1 * NSLOT + slot], (double)c);
    }
}

// ---------------------------------------------------------------------------
// Kernel B: warp-per-sample pairing on compacted boxes + last-CTA final.
// ---------------------------------------------------------------------------
__global__ __launch_bounds__(256) void yolo_pair_final_kernel(
    float* __restrict__ out, int B, int nctaB)
{
    const int tid  = threadIdx.x;
    const int lane = tid & 31;
    const int warp = tid >> 5;
    const int b    = blockIdx.x * 8 + warp;

    float coord = 0.f, objc = 0.f;

    if (b < B) {
        const int nbox = 2 * g_boxcnt[b];
        const float* base = g_boxes + (size_t)b * (CELLS * 20);

        for (int i = lane; i < nbox; i += 32) {
            const int roff = (i >> 1) * 20 + 5 * (i & 1);
            const float tcx = base[roff + 10], tcy = base[roff + 11];
            const float tw  = base[roff + 12], th  = base[roff + 13];
            const float tx0 = tcx - 0.5f * tw, ty0 = tcy - 0.5f * th;
            const float tx1 = tcx + 0.5f * tw, ty1 = tcy + 0.5f * th;

            bool found = false;
            for (int j = 0; j < nbox; j++) {
                const int po = (j >> 1) * 20 + 5 * (j & 1);
                const float pcx = base[po],     pcy = base[po + 1];
                const float pw  = base[po + 2], ph  = base[po + 3];
                const float ix = fminf(pcx + 0.5f * pw, tx1) - fmaxf(pcx - 0.5f * pw, tx0);
                const float iy = fminf(pcy + 0.5f * ph, ty1) - fmaxf(pcy - 0.5f * ph, ty0);
                found = found || (ix > 0.f && iy > 0.f && ix * iy > 0.f);
            }
            if (found) {
                const float dx = base[roff + 0] - tcx;
                const float dy = base[roff + 1] - tcy;
                const float dw = sqrtf(base[roff + 2]) - sqrtf(tw);
                const float dh = sqrtf(base[roff + 3]) - sqrtf(th);
                coord += dx * dx + dy * dy + dw * dw + dh * dh;
                const float dc = base[roff + 4] - base[roff + 14];
                objc += dc * dc;
            }
        }
    }

    #pragma unroll
    for (int o = 16; o > 0; o >>= 1) {
        coord += __shfl_down_sync(0xffffffffu, coord, o);
        objc  += __shfl_down_sync(0xffffffffu, objc, o);
    }
    __shared__ float sCo[8], sOb[8];
    __shared__ int s_last;
    if (lane == 0) {
        sCo[warp] = coord;
        sOb[warp] = objc;
        if (b < B) g_boxcnt[b] = 0;     // restore replay invariant
    }
    __syncthreads();

    if (tid == 0) {
        float pc = 0.f, po = 0.f;
        #pragma unroll
        for (int w = 0; w < 8; w++) { pc += sCo[w]; po += sOb[w]; }
        g_partB[blockIdx.x * 2 + 0] = pc;
        g_partB[blockIdx.x * 2 + 1] = po;
        __threadfence();
        const unsigned int old = atomicAdd(&g_count, 1u);
        s_last = (old == (unsigned int)(nctaB - 1)) ? 1 : 0;
    }
    __syncthreads();

    if (!s_last) return;

    // ---- final reduction (runs in exactly one CTA) ----
    double a0 = 0.0, a1 = 0.0, a2 = 0.0, a3 = 0.0;   // noobj, cls, coord, objc
    for (int i = tid; i < NSLOT; i += 256) {
        a0 += g_acc[0 * NSLOT + i];
        a1 += g_acc[1 * NSLOT + i];
        g_acc[0 * NSLOT + i] = 0.0;                   // restore
        g_acc[1 * NSLOT + i] = 0.0;
    }
    for (int i = tid; i < nctaB; i += 256) {
        a2 += (double)g_partB[i * 2 + 0];
        a3 += (double)g_partB[i * 2 + 1];
    }
    #pragma unroll
    for (int o = 16; o > 0; o >>= 1) {
        a0 += __shfl_down_sync(0xffffffffu, a0, o);
        a1 += __shfl_down_sync(0xffffffffu, a1, o);
        a2 += __shfl_down_sync(0xffffffffu, a2, o);
        a3 += __shfl_down_sync(0xffffffffu, a3, o);
    }
    __shared__ double sd[4][8];
    if (lane == 0) { sd[0][warp] = a0; sd[1][warp] = a1; sd[2][warp] = a2; sd[3][warp] = a3; }
    __syncthreads();
    if (tid == 0) {
        double r0 = 0, r1 = 0, r2 = 0, r3 = 0;
        #pragma unroll
        for (int w = 0; w < 8; w++) {
            r0 += sd[0][w]; r1 += sd[1][w]; r2 += sd[2][w]; r3 += sd[3][w];
        }
        const double inv = 1.0 / (double)B;
        const double cls_l = r1 * inv;
        const double obj_l = (r3 + 0.5 * r0) * inv;
        const double crd_l = r2 * 5.0 * inv;
        out[0] = (float)(cls_l + obj_l + crd_l);
        out[1] = (float)cls_l;
        out[2] = (float)obj_l;
        out[3] = (float)crd_l;
        g_count = 0u;                                  // restore replay invariant
    }
}

extern "C" void kernel_launch(void* const* d_in, const int* in_sizes, int n_in,
                              void* d_out, int out_size)
{
    const float* pred = (const float*)d_in[0];
    const float* target = (const float*)d_in[1];
    const int B = in_sizes[0] / FPS;
    const int ncells = B * CELLS;
    const int total_floats = B * FPS;
    const int nctaA = (ncells + CHUNK - 1) / CHUNK;
    const int nctaB = (B + 7) / 8;

    yolo_chunk_kernel<<<nctaA, 256>>>(pred, target, ncells, total_floats);
    yolo_pair_final_kernel<<<nctaB, 256>>>((float*)d_out, B, nctaB);
}

// round 5
// speedup vs baseline: 1.6758x; 1.1552x over previous
#include <cuda_runtime.h>
#include <math.h>

// YOLOv1 loss — bandwidth-saturating chunk kernel (A, unchanged from R4,
// measured ~16.8us at ~5.7TB/s) + rebuilt pairing kernel (B) that stages each
// sample's compacted box records into shared memory with coalesced float4
// loads before the O(nbox^2) existence test (R4's B was latency-bound on
// scattered scalar L2 reads: 26us at DRAM=3.6%).
//
// Exactness: max_iou is only compared against 0 and union>0 always
// (w,h >= 0.05), so cmask == "exists masked pred box with intersection > 0".
// Intersection arithmetic (cx - 0.5f*w, min/max/sub, >0) matches the
// reference's ops exactly; box floats pass through scratch unmodified.
//
// Graph-replay invariants: g_acc / g_boxcnt / g_count are zero at every
// launch; kernel B's last CTA restores all of them.

#define CELLS 49
#define CH 30
#define FPS (CELLS * CH)        // 1470 floats per sample
#define CHUNK 64                // cells per CTA in kernel A
#define CHUNK_F (CHUNK * CH)    // 1920 floats
#define MAXB 8192
#define NSLOT 128
#define RECF 980                // 49 cells * 20 floats per sample record block
#define WARPS_B 8
#define NCTA_B_MAX ((MAXB + WARPS_B - 1) / WARPS_B)

__device__ float  g_boxes[MAXB * RECF];             // compacted obj-box records
__device__ int    g_boxcnt[MAXB];                   // boxes per sample (zeroed by B)
__device__ double g_acc[2 * NSLOT];                 // [0]=noobj [1]=cls (zeroed by B)
__device__ float  g_partB[NCTA_B_MAX * 2];          // per-CTA coord/objc partials
__device__ unsigned int g_count = 0;

// ---------------------------------------------------------------------------
// Kernel A: one CTA per 64-cell chunk. float4 staging -> per-cell compute.
// ---------------------------------------------------------------------------
__global__ __launch_bounds__(256) void yolo_chunk_kernel(
    const float* __restrict__ pred, const float* __restrict__ target,
    int ncells, int total_floats)
{
    __shared__ float sp[CHUNK_F];
    __shared__ float st[CHUNK_F];
    __shared__ float sN[8], sC[8];

    const int tid  = threadIdx.x;
    const int c0   = blockIdx.x * CHUNK;
    const int f0   = c0 * CH;                         // 1920*blk -> 16B aligned
    const int flen = min(CHUNK_F, total_floats - f0);

    {
        const int nv4 = flen >> 2;
        const float4* gp4 = (const float4*)(pred + f0);
        const float4* gt4 = (const float4*)(target + f0);
        float4* sp4 = (float4*)sp;
        float4* st4 = (float4*)st;
        #pragma unroll 2
        for (int i = tid; i < nv4; i += 256) {
            sp4[i] = gp4[i];
            st4[i] = gt4[i];
        }
        for (int i = (nv4 << 2) + tid; i < flen; i += 256) {
            sp[i] = pred[f0 + i];
            st[i] = target[f0 + i];
        }
    }
    __syncthreads();

    float accN = 0.f, accC = 0.f;
    if (tid < CHUNK && c0 + tid < ncells) {
        const int cell = c0 + tid;
        const float* pc = sp + tid * CH;
        const float* tc = st + tid * CH;
        if (tc[4] == 0.f) {
            const float d4 = pc[4] - tc[4];
            const float d9 = pc[9] - tc[9];
            accN = d4 * d4 + d9 * d9;
        } else {
            float s = 0.f;
            #pragma unroll
            for (int k = 10; k < CH; k++) {
                const float d = pc[k] - tc[k];
                s += d * d;
            }
            accC = s;
            const int b = cell / CELLS;
            const int slot = atomicAdd(&g_boxcnt[b], 1);
            float* rec = g_boxes + (size_t)b * RECF + slot * 20;
            #pragma unroll
            for (int k = 0; k < 10; k++) {
                rec[k]      = pc[k];
                rec[10 + k] = tc[k];
            }
        }
    }

    #pragma unroll
    for (int o = 16; o > 0; o >>= 1) {
        accN += __shfl_down_sync(0xffffffffu, accN, o);
        accC += __shfl_down_sync(0xffffffffu, accC, o);
    }
    const int lane = tid & 31, warp = tid >> 5;
    if (lane == 0) { sN[warp] = accN; sC[warp] = accC; }
    __syncthreads();
    if (tid == 0) {
        float n = 0.f, c = 0.f;
        #pragma unroll
        for (int w = 0; w < 8; w++) { n += sN[w]; c += sC[w]; }
        const int slot = blockIdx.x & (NSLOT - 1);
        atomicAdd(&g_acc[0 * NSLOT + slot], (double)n);
        atomicAdd(&g_acc[1 * NSLOT + slot], (double)c);
    }
}

// ---------------------------------------------------------------------------
// Kernel B: warp-per-sample pairing with smem-staged records + last-CTA final.
// ---------------------------------------------------------------------------
__global__ __launch_bounds__(32 * WARPS_B) void yolo_pair_final_kernel(
    float* __restrict__ out, int B, int nctaB)
{
    __shared__ float sbox[WARPS_B][RECF];
    __shared__ float sCo[WARPS_B], sOb[WARPS_B];
    __shared__ int s_last;

    const int tid  = threadIdx.x;
    const int lane = tid & 31;
    const int warp = tid >> 5;
    const int b    = blockIdx.x * WARPS_B + warp;

    float coord = 0.f, objc = 0.f;

    if (b < B) {
        const int cnt  = g_boxcnt[b];
        const int nbox = 2 * cnt;

        // ---- coalesced float4 staging of this sample's records ----
        const int nf4 = cnt * 5;                      // cnt*20 floats / 4
        const float4* src = (const float4*)(g_boxes + (size_t)b * RECF);
        float4* dst = (float4*)sbox[warp];
        for (int i = lane; i < nf4; i += 32)
            dst[i] = src[i];
        __syncwarp();

        const float* base = sbox[warp];
        for (int i = lane; i < nbox; i += 32) {
            const int roff = (i >> 1) * 20 + 5 * (i & 1);
            const float tcx = base[roff + 10], tcy = base[roff + 11];
            const float tw  = base[roff + 12], th  = base[roff + 13];
            const float tx0 = tcx - 0.5f * tw, ty0 = tcy - 0.5f * th;
            const float tx1 = tcx + 0.5f * tw, ty1 = tcy + 0.5f * th;

            bool found = false;
            for (int j = 0; j < nbox; j++) {          // j uniform -> smem broadcast
                const int po = (j >> 1) * 20 + 5 * (j & 1);
                const float pcx = base[po],     pcy = base[po + 1];
                const float pw  = base[po + 2], ph  = base[po + 3];
                const float ix = fminf(pcx + 0.5f * pw, tx1) - fmaxf(pcx - 0.5f * pw, tx0);
                const float iy = fminf(pcy + 0.5f * ph, ty1) - fmaxf(pcy - 0.5f * ph, ty0);
                found = found || (ix > 0.f && iy > 0.f && ix * iy > 0.f);
            }
            if (found) {
                const float dx = base[roff + 0] - tcx;
                const float dy = base[roff + 1] - tcy;
                const float dw = sqrtf(base[roff + 2]) - sqrtf(tw);
                const float dh = sqrtf(base[roff + 3]) - sqrtf(th);
                coord += dx * dx + dy * dy + dw * dw + dh * dh;
                const float dc = base[roff + 4] - base[roff + 14];
                objc += dc * dc;
            }
        }
    }

    #pragma unroll
    for (int o = 16; o > 0; o >>= 1) {
        coord += __shfl_down_sync(0xffffffffu, coord, o);
        objc  += __shfl_down_sync(0xffffffffu, objc, o);
    }
    if (lane == 0) {
        sCo[warp] = coord;
        sOb[warp] = objc;
        if (b < B) g_boxcnt[b] = 0;                   // restore replay invariant
    }
    __syncthreads();

    if (tid == 0) {
        float pc = 0.f, po = 0.f;
        #pragma unroll
        for (int w = 0; w < WARPS_B; w++) { pc += sCo[w]; po += sOb[w]; }
        g_partB[blockIdx.x * 2 + 0] = pc;
        g_partB[blockIdx.x * 2 + 1] = po;
        __threadfence();
        const unsigned int old = atomicAdd(&g_count, 1u);
        s_last = (old == (unsigned int)(nctaB - 1)) ? 1 : 0;
    }
    __syncthreads();

    if (!s_last) return;

    // ---- final reduction (one CTA) ----
    double a0 = 0.0, a1 = 0.0, a2 = 0.0, a3 = 0.0;
    for (int i = tid; i < NSLOT; i += 32 * WARPS_B) {
        a0 += g_acc[0 * NSLOT + i];
        a1 += g_acc[1 * NSLOT + i];
        g_acc[0 * NSLOT + i] = 0.0;
        g_acc[1 * NSLOT + i] = 0.0;
    }
    for (int i = tid; i < nctaB; i += 32 * WARPS_B) {
        a2 += (double)g_partB[i * 2 + 0];
        a3 += (double)g_partB[i * 2 + 1];
    }
    #pragma unroll
    for (int o = 16; o > 0; o >>= 1) {
        a0 += __shfl_down_sync(0xffffffffu, a0, o);
        a1 += __shfl_down_sync(0xffffffffu, a1, o);
        a2 += __shfl_down_sync(0xffffffffu, a2, o);
        a3 += __shfl_down_sync(0xffffffffu, a3, o);
    }
    __shared__ double sd[4][WARPS_B];
    if (lane == 0) { sd[0][warp] = a0; sd[1][warp] = a1; sd[2][warp] = a2; sd[3][warp] = a3; }
    __syncthreads();
    if (tid == 0) {
        double r0 = 0, r1 = 0, r2 = 0, r3 = 0;
        #pragma unroll
        for (int w = 0; w < WARPS_B; w++) {
            r0 += sd[0][w]; r1 += sd[1][w]; r2 += sd[2][w]; r3 += sd[3][w];
        }
        const double inv = 1.0 / (double)B;
        const double cls_l = r1 * inv;
        const double obj_l = (r3 + 0.5 * r0) * inv;
        const double crd_l = r2 * 5.0 * inv;
        out[0] = (float)(cls_l + obj_l + crd_l);
        out[1] = (float)cls_l;
        out[2] = (float)obj_l;
        out[3] = (float)crd_l;
        g_count = 0u;
    }
}

extern "C" void kernel_launch(void* const* d_in, const int* in_sizes, int n_in,
                              void* d_out, int out_size)
{
    const float* pred = (const float*)d_in[0];
    const float* target = (const float*)d_in[1];
    const int B = in_sizes[0] / FPS;
    const int ncells = B * CELLS;
    const int total_floats = B * FPS;
    const int nctaA = (ncells + CHUNK - 1) / CHUNK;
    const int nctaB = (B + WARPS_B - 1) / WARPS_B;

    yolo_chunk_kernel<<<nctaA, 256>>>(pred, target, ncells, total_floats);
    yolo_pair_final_kernel<<<nctaB, 32 * WARPS_B>>>((float*)d_out, B, nctaB);
}